// round 1
// baseline (speedup 1.0000x reference)
#include <cuda_runtime.h>
#include <cuda_bf16.h>
#include <math_constants.h>

// Problem constants
#define BB 2
#define SS 2048
#define DD 1024
#define HH 16
#define DH 64
#define MM (BB * SS)   // 4096 rows for projections

// ---------------------------------------------------------------------------
// Scratch: projected Q, K, V  (each [B,S,D] fp32 = 16 MB)
// ---------------------------------------------------------------------------
__device__ float g_Q[MM * DD];
__device__ float g_K[MM * DD];
__device__ float g_V[MM * DD];

// ---------------------------------------------------------------------------
// SGEMM with bias:  C[M,N] = A[M,K] @ W[K,N] + bias[N]
// BM=128, BN=128, BK=16, 256 threads, 8x8 register tile per thread
// ---------------------------------------------------------------------------
#define GBM 128
#define GBN 128
#define GBK 16
#define GTM 8
#define GTN 8

__global__ void __launch_bounds__(256)
sgemm_bias(const float* __restrict__ A, const float* __restrict__ W,
           const float* __restrict__ bias, float* __restrict__ C,
           int M, int N, int K)
{
    __shared__ float As[GBK][GBM + 4];   // stored transposed: As[k][m]
    __shared__ float Bs[GBK][GBN];

    const int tid = threadIdx.x;
    const int tx = tid & 15;    // 0..15 -> N direction
    const int ty = tid >> 4;    // 0..15 -> M direction
    const int bx = blockIdx.x;  // N tile
    const int by = blockIdx.y;  // M tile

    const float* Aptr = A + (size_t)(by * GBM) * K;
    const float* Wptr = W + bx * GBN;

    // A tile loads: 128 rows x 16 k = 512 float4, 2 per thread
    const int arow  = tid >> 2;        // 0..63 (+64)
    const int acol4 = tid & 3;         // float4 index, col = acol4*4
    // B tile loads: 16 k x 128 n = 512 float4, 2 per thread
    const int brow  = tid >> 5;        // 0..7 (+8)
    const int bcol4 = tid & 31;        // col = bcol4*4

    float acc[GTM][GTN] = {};

    for (int k0 = 0; k0 < K; k0 += GBK) {
        #pragma unroll
        for (int r = 0; r < 2; r++) {
            int m = arow + r * 64;
            float4 v = *(const float4*)(Aptr + (size_t)m * K + k0 + acol4 * 4);
            As[acol4 * 4 + 0][m] = v.x;
            As[acol4 * 4 + 1][m] = v.y;
            As[acol4 * 4 + 2][m] = v.z;
            As[acol4 * 4 + 3][m] = v.w;
        }
        #pragma unroll
        for (int r = 0; r < 2; r++) {
            int k = brow + r * 8;
            float4 v = *(const float4*)(Wptr + (size_t)(k0 + k) * N + bcol4 * 4);
            *(float4*)&Bs[k][bcol4 * 4] = v;
        }
        __syncthreads();

        #pragma unroll
        for (int k = 0; k < GBK; k++) {
            float a[GTM], b[GTN];
            #pragma unroll
            for (int i = 0; i < GTM; i++) a[i] = As[k][ty * GTM + i];
            #pragma unroll
            for (int j = 0; j < GTN; j++) b[j] = Bs[k][tx * GTN + j];
            #pragma unroll
            for (int i = 0; i < GTM; i++)
                #pragma unroll
                for (int j = 0; j < GTN; j++)
                    acc[i][j] += a[i] * b[j];
        }
        __syncthreads();
    }

    // epilogue: add bias, store
    #pragma unroll
    for (int i = 0; i < GTM; i++) {
        int m = by * GBM + ty * GTM + i;
        #pragma unroll
        for (int j = 0; j < GTN; j += 4) {
            int n = bx * GBN + tx * GTN + j;
            float4 o;
            o.x = acc[i][j + 0] + bias[n + 0];
            o.y = acc[i][j + 1] + bias[n + 1];
            o.z = acc[i][j + 2] + bias[n + 2];
            o.w = acc[i][j + 3] + bias[n + 3];
            *(float4*)(C + (size_t)m * N + n) = o;
        }
    }
}

// ---------------------------------------------------------------------------
// Flash attention, fp32.
// One CTA per (query-tile of 64, head, batch). 256 threads.
// Thread (ty,tx): rows m = ty*4+i, cols c = tx + j*16 (row/col of the 64x64
// tile). All smem buffers use row stride 65 (odd) => stride-1 lane access
// across rows is bank-conflict-free.
// ---------------------------------------------------------------------------
#define AST 65                 // smem row stride
#define ASM_FLOATS (4 * 64 * AST)

__global__ void __launch_bounds__(256)
attn_kernel(const float* __restrict__ Q, const float* __restrict__ Kg,
            const float* __restrict__ Vg, const float* __restrict__ Xres,
            float* __restrict__ Out)
{
    extern __shared__ float sm[];
    float* Qs = sm;                  // [64][65]
    float* Ks = Qs + 64 * AST;
    float* Vs = Ks + 64 * AST;
    float* Ps = Vs + 64 * AST;

    const int tid = threadIdx.x;
    const int tx = tid & 15;
    const int ty = tid >> 4;
    const int qt = blockIdx.x;          // query tile (0..31)
    const int h  = blockIdx.y % HH;
    const int b  = blockIdx.y / HH;
    const int s0 = qt * 64;

    const size_t headoff = (size_t)b * SS * DD + (size_t)h * DH;

    // Load Q tile [64 x 64]
    {
        const int r  = tid >> 4;     // 0..15
        const int c4 = tid & 15;     // float4 column index
        #pragma unroll
        for (int it = 0; it < 4; it++) {
            int row = r + it * 16;
            float4 v = *(const float4*)(Q + headoff + (size_t)(s0 + row) * DD + c4 * 4);
            float* dst = Qs + row * AST + c4 * 4;
            dst[0] = v.x; dst[1] = v.y; dst[2] = v.z; dst[3] = v.w;
        }
    }

    float o[4][4] = {};
    float mrow[4] = {-CUDART_INF_F, -CUDART_INF_F, -CUDART_INF_F, -CUDART_INF_F};
    float lrow[4] = {};
    const float scale = 0.125f;   // 1/sqrt(64)

    for (int n0 = 0; n0 < SS; n0 += 64) {
        __syncthreads();   // previous iteration's P@V done before reloading K/V

        // Load K and V tiles [64 x 64]
        {
            const int r  = tid >> 4;
            const int c4 = tid & 15;
            #pragma unroll
            for (int it = 0; it < 4; it++) {
                int row = r + it * 16;
                size_t goff = headoff + (size_t)(n0 + row) * DD + c4 * 4;
                float4 vk = *(const float4*)(Kg + goff);
                float* dk = Ks + row * AST + c4 * 4;
                dk[0] = vk.x; dk[1] = vk.y; dk[2] = vk.z; dk[3] = vk.w;
                float4 vv = *(const float4*)(Vg + goff);
                float* dv = Vs + row * AST + c4 * 4;
                dv[0] = vv.x; dv[1] = vv.y; dv[2] = vv.z; dv[3] = vv.w;
            }
        }
        __syncthreads();

        // S = Q @ K^T  (64x64 tile, 4x4 per thread)
        float s[4][4] = {};
        #pragma unroll
        for (int d = 0; d < DH; d++) {
            float q[4], k[4];
            #pragma unroll
            for (int i = 0; i < 4; i++) q[i] = Qs[(ty * 4 + i) * AST + d];
            #pragma unroll
            for (int j = 0; j < 4; j++) k[j] = Ks[(tx + j * 16) * AST + d];
            #pragma unroll
            for (int i = 0; i < 4; i++)
                #pragma unroll
                for (int j = 0; j < 4; j++)
                    s[i][j] += q[i] * k[j];
        }

        // Online softmax per row; write P to smem
        #pragma unroll
        for (int i = 0; i < 4; i++) {
            float mx = -CUDART_INF_F;
            #pragma unroll
            for (int j = 0; j < 4; j++) {
                s[i][j] *= scale;
                mx = fmaxf(mx, s[i][j]);
            }
            #pragma unroll
            for (int off = 8; off >= 1; off >>= 1)
                mx = fmaxf(mx, __shfl_xor_sync(0xffffffffu, mx, off));
            float mnew = fmaxf(mrow[i], mx);
            float corr = __expf(mrow[i] - mnew);
            float rs = 0.f;
            #pragma unroll
            for (int j = 0; j < 4; j++) {
                float p = __expf(s[i][j] - mnew);
                s[i][j] = p;
                rs += p;
            }
            #pragma unroll
            for (int off = 8; off >= 1; off >>= 1)
                rs += __shfl_xor_sync(0xffffffffu, rs, off);
            lrow[i] = lrow[i] * corr + rs;
            mrow[i] = mnew;
            #pragma unroll
            for (int j = 0; j < 4; j++) o[i][j] *= corr;
            #pragma unroll
            for (int j = 0; j < 4; j++)
                Ps[(ty * 4 + i) * AST + tx + j * 16] = s[i][j];
        }
        __syncthreads();

        // O += P @ V
        #pragma unroll
        for (int n = 0; n < 64; n++) {
            float p[4], v[4];
            #pragma unroll
            for (int i = 0; i < 4; i++) p[i] = Ps[(ty * 4 + i) * AST + n];
            #pragma unroll
            for (int j = 0; j < 4; j++) v[j] = Vs[n * AST + tx + j * 16];
            #pragma unroll
            for (int i = 0; i < 4; i++)
                #pragma unroll
                for (int j = 0; j < 4; j++)
                    o[i][j] += p[i] * v[j];
        }
    }

    // Epilogue: normalize, add residual, store
    #pragma unroll
    for (int i = 0; i < 4; i++) {
        float inv = 1.0f / lrow[i];
        int m = ty * 4 + i;
        #pragma unroll
        for (int j = 0; j < 4; j++) {
            int d = tx + j * 16;
            size_t idx = headoff + (size_t)(s0 + m) * DD + d;
            Out[idx] = o[i][j] * inv + Xres[idx];
        }
    }
}

// ---------------------------------------------------------------------------
// Launch
// ---------------------------------------------------------------------------
extern "C" void kernel_launch(void* const* d_in, const int* in_sizes, int n_in,
                              void* d_out, int out_size)
{
    const float* queries = (const float*)d_in[0];
    const float* keys    = (const float*)d_in[1];
    const float* values  = (const float*)d_in[2];
    const float* Wq      = (const float*)d_in[3];
    const float* bq      = (const float*)d_in[4];
    const float* Wk      = (const float*)d_in[5];
    const float* bk      = (const float*)d_in[6];
    const float* Wv      = (const float*)d_in[7];
    const float* bv      = (const float*)d_in[8];
    float* out           = (float*)d_out;

    float *dQ, *dK, *dV;
    cudaGetSymbolAddress((void**)&dQ, g_Q);
    cudaGetSymbolAddress((void**)&dK, g_K);
    cudaGetSymbolAddress((void**)&dV, g_V);

    // Projections: [4096,1024] @ [1024,1024] + bias
    dim3 ggrid(DD / GBN, MM / GBM);   // (8, 32)
    sgemm_bias<<<ggrid, 256>>>(queries, Wq, bq, dQ, MM, DD, DD);
    sgemm_bias<<<ggrid, 256>>>(keys,    Wk, bk, dK, MM, DD, DD);
    sgemm_bias<<<ggrid, 256>>>(values,  Wv, bv, dV, MM, DD, DD);

    // Attention: 32 query tiles x (H*B = 32)
    const int smem_bytes = ASM_FLOATS * sizeof(float);  // 66560
    static bool attr_set = false;
    cudaFuncSetAttribute(attn_kernel,
                         cudaFuncAttributeMaxDynamicSharedMemorySize, smem_bytes);
    (void)attr_set;
    dim3 agrid(SS / 64, HH * BB);     // (32, 32)
    attn_kernel<<<agrid, 256, smem_bytes>>>(dQ, dK, dV, queries, out);
}

// round 3
// speedup vs baseline: 6.5333x; 6.5333x over previous
#include <cuda_runtime.h>
#include <cuda_bf16.h>
#include <math_constants.h>
#include <cstdint>

// Problem constants
#define BB 2
#define SS 2048
#define DD 1024
#define HH 16
#define DH 64
#define MM (BB * SS)   // 4096 rows for projections

// ---------------------------------------------------------------------------
// Scratch buffers (__device__ globals; no allocation allowed)
// g_Q/g_K/g_V hold the bf16 projected Q,K,V (reusing fp32-sized storage)
// ---------------------------------------------------------------------------
__device__ __nv_bfloat16 g_Qp[MM * DD];
__device__ __nv_bfloat16 g_Kp[MM * DD];
__device__ __nv_bfloat16 g_Vp[MM * DD];
__device__ __nv_bfloat16 g_Qb[MM * DD];    // bf16 inputs
__device__ __nv_bfloat16 g_Kb[MM * DD];
__device__ __nv_bfloat16 g_Vb[MM * DD];
__device__ __nv_bfloat16 g_Wqt[DD * DD];   // W^T bf16: [n][k]
__device__ __nv_bfloat16 g_Wkt[DD * DD];
__device__ __nv_bfloat16 g_Wvt[DD * DD];

// ---------------------------------------------------------------------------
// PTX helpers (arch-portable: ldmatrix / mma.sync / cp.async)
// ---------------------------------------------------------------------------
__device__ __forceinline__ uint32_t smem_u32(const void* p) {
    uint32_t a;
    asm("{ .reg .u64 t; cvta.to.shared.u64 t, %1; cvt.u32.u64 %0, t; }"
        : "=r"(a) : "l"(p));
    return a;
}

__device__ __forceinline__ void ldsm_x4(uint32_t* r, uint32_t addr) {
    asm volatile("ldmatrix.sync.aligned.m8n8.x4.shared.b16 {%0,%1,%2,%3}, [%4];"
                 : "=r"(r[0]), "=r"(r[1]), "=r"(r[2]), "=r"(r[3]) : "r"(addr));
}
__device__ __forceinline__ void ldsm_x4_t(uint32_t* r, uint32_t addr) {
    asm volatile("ldmatrix.sync.aligned.m8n8.x4.trans.shared.b16 {%0,%1,%2,%3}, [%4];"
                 : "=r"(r[0]), "=r"(r[1]), "=r"(r[2]), "=r"(r[3]) : "r"(addr));
}
__device__ __forceinline__ void mma_bf16(float* c, const uint32_t* a, const uint32_t* b) {
    asm volatile(
        "mma.sync.aligned.m16n8k16.row.col.f32.bf16.bf16.f32 "
        "{%0,%1,%2,%3}, {%4,%5,%6,%7}, {%8,%9}, {%0,%1,%2,%3};"
        : "+f"(c[0]), "+f"(c[1]), "+f"(c[2]), "+f"(c[3])
        : "r"(a[0]), "r"(a[1]), "r"(a[2]), "r"(a[3]), "r"(b[0]), "r"(b[1]));
}

#define CP_ASYNC16(dst_u32, src_ptr) \
    asm volatile("cp.async.cg.shared.global [%0], [%1], 16;" \
                 :: "r"(dst_u32), "l"(src_ptr))
#define CP_COMMIT() asm volatile("cp.async.commit_group;" ::: "memory")
#define CP_WAIT_1() asm volatile("cp.async.wait_group 1;" ::: "memory")
#define CP_WAIT_0() asm volatile("cp.async.wait_group 0;" ::: "memory")

#define SW128(off) ((uint32_t)(off) ^ ((((uint32_t)(off)) >> 3) & 0x70u))

// ---------------------------------------------------------------------------
// Conversion kernels
// ---------------------------------------------------------------------------
__global__ void __launch_bounds__(256)
f32_to_bf16_kernel(const float* __restrict__ in, __nv_bfloat16* __restrict__ out)
{
    int i = (blockIdx.x * 256 + threadIdx.x) * 4;
    float4 v = *(const float4*)(in + i);
    __nv_bfloat162* o2 = (__nv_bfloat162*)(out + i);
    o2[0] = __floats2bfloat162_rn(v.x, v.y);
    o2[1] = __floats2bfloat162_rn(v.z, v.w);
}

// Wt[n][k] = bf16(W[k][n]); W is [DD,DD] fp32 row-major
__global__ void __launch_bounds__(256)
transpose_to_bf16_kernel(const float* __restrict__ W, __nv_bfloat16* __restrict__ Wt)
{
    __shared__ float t[32][33];
    const int tx = threadIdx.x;
    const int ty = threadIdx.y;
    const int bx = blockIdx.x * 32;
    const int by = blockIdx.y * 32;
    #pragma unroll
    for (int i = 0; i < 4; i++)
        t[ty + i * 8][tx] = W[(size_t)(by + ty + i * 8) * DD + bx + tx];
    __syncthreads();
    #pragma unroll
    for (int i = 0; i < 4; i++)
        Wt[(size_t)(bx + ty + i * 8) * DD + by + tx] =
            __float2bfloat16(t[tx][ty + i * 8]);
}

// ---------------------------------------------------------------------------
// bf16 HMMA GEMM + bias, bf16 output.
// C[M,N] = A[M,K] @ Bt[N,K]^T + bias.  Tile 128x128, K-stage 64, 8 warps (2x4).
// cp.async 2-stage pipeline, SW128 swizzled smem.
// ---------------------------------------------------------------------------
#define PBM 128
#define PBN 128
#define PBK 64
#define PKT (DD / PBK)     // 16 k-tiles
#define PSTG 16384         // bytes per A or B stage (128 x 128B)
#define GEMM_SMEM (4 * PSTG + 128)

__global__ void __launch_bounds__(256)
gemm_bias_mma(const __nv_bfloat16* __restrict__ A,
              const __nv_bfloat16* __restrict__ Bt,
              const float* __restrict__ bias,
              __nv_bfloat16* __restrict__ C)
{
    extern __shared__ char dyn[];
    const uint32_t sb = (smem_u32(dyn) + 127u) & ~127u;

    const int tid = threadIdx.x;
    const int lane = tid & 31;
    const int wid = tid >> 5;
    const int wm = wid >> 2;          // 0..1  (64 rows each)
    const int wn = wid & 3;           // 0..3  (32 cols each)
    const int n0 = blockIdx.x * PBN;
    const int m0 = blockIdx.y * PBM;

    // per-thread load geometry: 4 chunks of 16B for A, 4 for B per stage
    const int ldrow = tid >> 3;       // +32 per iter? no: id = tid + c*256 -> row=id>>3
    const int ldc16 = tid & 7;

    // ldmatrix lane geometry
    const int rA = (lane & 7) + ((lane >> 3) & 1) * 8;
    const int kbA = (lane >> 4) * 16;
    const int rB = (lane & 7) + (lane >> 4) * 8;
    const int kbB = ((lane >> 3) & 1) * 16;

#define PROJ_ISSUE(T, BUF) do { \
    const uint32_t as_ = sb + (BUF) * 2 * PSTG; \
    const uint32_t bs_ = as_ + PSTG; \
    _Pragma("unroll") \
    for (int c = 0; c < 4; ++c) { \
        int id = tid + c * 256; \
        int row = id >> 3, c16 = id & 7; \
        uint32_t so = SW128(row * 128 + c16 * 16); \
        CP_ASYNC16(as_ + so, A  + (size_t)(m0 + row) * DD + (T) * PBK + c16 * 8); \
        CP_ASYNC16(bs_ + so, Bt + (size_t)(n0 + row) * DD + (T) * PBK + c16 * 8); \
    } \
} while (0)

    float acc[4][4][4] = {};

    PROJ_ISSUE(0, 0); CP_COMMIT();
    PROJ_ISSUE(1, 1); CP_COMMIT();
    CP_WAIT_1();
    __syncthreads();

    for (int t = 0; t < PKT; ++t) {
        const uint32_t as_ = sb + (t & 1) * 2 * PSTG;
        const uint32_t bs_ = as_ + PSTG;
        #pragma unroll
        for (int kk = 0; kk < 4; ++kk) {
            uint32_t af[4][4], bf[2][4];
            #pragma unroll
            for (int i = 0; i < 4; ++i)
                ldsm_x4(af[i], as_ + SW128((wm * 64 + i * 16 + rA) * 128 + kk * 32 + kbA));
            #pragma unroll
            for (int n16 = 0; n16 < 2; ++n16)
                ldsm_x4(bf[n16], bs_ + SW128((wn * 32 + n16 * 16 + rB) * 128 + kk * 32 + kbB));
            #pragma unroll
            for (int i = 0; i < 4; ++i)
                #pragma unroll
                for (int nb = 0; nb < 4; ++nb)
                    mma_bf16(acc[i][nb], af[i], &bf[nb >> 1][2 * (nb & 1)]);
        }
        __syncthreads();
        if (t + 2 < PKT) {
            PROJ_ISSUE(t + 2, t & 1); CP_COMMIT();
            CP_WAIT_1();
            __syncthreads();
        } else if (t + 1 < PKT) {
            CP_WAIT_0();
            __syncthreads();
        }
    }
#undef PROJ_ISSUE

    // Epilogue: + bias, write bf16
    const int gg = lane >> 2, cc = lane & 3;
    #pragma unroll
    for (int i = 0; i < 4; ++i) {
        int r0 = m0 + wm * 64 + i * 16 + gg;
        #pragma unroll
        for (int nb = 0; nb < 4; ++nb) {
            int cn = n0 + wn * 32 + nb * 8 + 2 * cc;
            float2 bi = *(const float2*)(bias + cn);
            *(__nv_bfloat162*)(C + (size_t)r0 * DD + cn) =
                __floats2bfloat162_rn(acc[i][nb][0] + bi.x, acc[i][nb][1] + bi.y);
            *(__nv_bfloat162*)(C + (size_t)(r0 + 8) * DD + cn) =
                __floats2bfloat162_rn(acc[i][nb][2] + bi.x, acc[i][nb][3] + bi.y);
        }
    }
    (void)ldrow; (void)ldc16;
}

// ---------------------------------------------------------------------------
// Flash attention, bf16 HMMA.
// CTA = 128 q-rows x (head,batch); 8 warps, warp owns m16.
// Q frags preloaded in registers; K ldmatrix; V ldmatrix.trans; P in regs.
// ---------------------------------------------------------------------------
#define AQM 128
#define AKN 64
#define NKV (SS / AKN)     // 32 kv tiles
// smem: Qs 16KB | K0 8K | V0 8K | K1 8K | V1 8K = 48KB
#define AOFF_Q 0
#define AOFF_K(b) (16384 + (b) * 16384)
#define AOFF_V(b) (16384 + (b) * 16384 + 8192)
#define ATTN_SMEM (49152 + 128)

__global__ void __launch_bounds__(256)
attn_mma(const __nv_bfloat16* __restrict__ Qp, const __nv_bfloat16* __restrict__ Kp,
         const __nv_bfloat16* __restrict__ Vp, const float* __restrict__ Xres,
         float* __restrict__ Out)
{
    extern __shared__ char dyn[];
    const uint32_t sb = (smem_u32(dyn) + 127u) & ~127u;

    const int tid = threadIdx.x;
    const int lane = tid & 31;
    const int wid = tid >> 5;
    const int qt = blockIdx.x;
    const int h  = blockIdx.y % HH;
    const int b  = blockIdx.y / HH;
    const int s0 = qt * AQM;
    const size_t headoff = (size_t)b * SS * DD + (size_t)h * DH;

    // ldmatrix lane geometry
    const int rA = (lane & 7) + ((lane >> 3) & 1) * 8;   // A (non-trans)
    const int kbA = (lane >> 4) * 16;
    const int rB = (lane & 7) + (lane >> 4) * 8;         // B (non-trans, K)
    const int kbB = ((lane >> 3) & 1) * 16;
    const int rV = (lane & 7) + ((lane >> 3) & 1) * 8;   // V (trans): k rows
    const int nbV = (lane >> 4) * 16;                    // n byte off

    // ---- issue Q tile + KV tile 0 (group 0), KV tile 1 (group 1) ----
    {
        #pragma unroll
        for (int c = 0; c < 4; ++c) {
            int id = tid + c * 256;
            int row = id >> 3, c16 = id & 7;
            CP_ASYNC16(sb + AOFF_Q + SW128(row * 128 + c16 * 16),
                       Qp + headoff + (size_t)(s0 + row) * DD + c16 * 8);
        }
    }
#define KV_ISSUE(T, BUF) do { \
    _Pragma("unroll") \
    for (int c = 0; c < 2; ++c) { \
        int id = tid + c * 256; \
        int row = id >> 3, c16 = id & 7; \
        uint32_t so = SW128(row * 128 + c16 * 16); \
        size_t go = headoff + (size_t)((T) * AKN + row) * DD + c16 * 8; \
        CP_ASYNC16(sb + AOFF_K(BUF) + so, Kp + go); \
        CP_ASYNC16(sb + AOFF_V(BUF) + so, Vp + go); \
    } \
} while (0)
    KV_ISSUE(0, 0); CP_COMMIT();
    KV_ISSUE(1, 1); CP_COMMIT();
    CP_WAIT_1();
    __syncthreads();

    // ---- preload Q fragments (held for entire kernel) ----
    uint32_t qa[4][4];
    #pragma unroll
    for (int kk = 0; kk < 4; ++kk)
        ldsm_x4(qa[kk], sb + AOFF_Q + SW128((wid * 16 + rA) * 128 + kk * 32 + kbA));

    float Oacc[8][4] = {};
    float mrow[2] = {-CUDART_INF_F, -CUDART_INF_F};
    float lrow[2] = {0.f, 0.f};
    const float scale = 0.125f;

    for (int t = 0; t < NKV; ++t) {
        const uint32_t ks_ = sb + AOFF_K(t & 1);
        const uint32_t vs_ = sb + AOFF_V(t & 1);

        // ---- S = Q @ K^T ----
        float Sacc[8][4] = {};
        #pragma unroll
        for (int kk = 0; kk < 4; ++kk) {
            uint32_t bk[4][4];
            #pragma unroll
            for (int n16 = 0; n16 < 4; ++n16)
                ldsm_x4(bk[n16], ks_ + SW128((n16 * 16 + rB) * 128 + kk * 32 + kbB));
            #pragma unroll
            for (int j = 0; j < 8; ++j)
                mma_bf16(Sacc[j], qa[kk], &bk[j >> 1][2 * (j & 1)]);
        }

        // ---- online softmax (rows g, g+8) ----
        float mloc[2] = {-CUDART_INF_F, -CUDART_INF_F};
        #pragma unroll
        for (int j = 0; j < 8; ++j)
            #pragma unroll
            for (int x = 0; x < 4; ++x) {
                float v = Sacc[j][x] * scale;
                Sacc[j][x] = v;
                mloc[x >> 1] = fmaxf(mloc[x >> 1], v);
            }
        #pragma unroll
        for (int r = 0; r < 2; ++r) {
            mloc[r] = fmaxf(mloc[r], __shfl_xor_sync(0xffffffffu, mloc[r], 1));
            mloc[r] = fmaxf(mloc[r], __shfl_xor_sync(0xffffffffu, mloc[r], 2));
        }
        float mnew[2], corr[2], psum[2] = {0.f, 0.f};
        #pragma unroll
        for (int r = 0; r < 2; ++r) {
            mnew[r] = fmaxf(mrow[r], mloc[r]);
            corr[r] = __expf(mrow[r] - mnew[r]);
        }
        #pragma unroll
        for (int j = 0; j < 8; ++j)
            #pragma unroll
            for (int x = 0; x < 4; ++x) {
                float p = __expf(Sacc[j][x] - mnew[x >> 1]);
                Sacc[j][x] = p;
                psum[x >> 1] += p;
            }
        #pragma unroll
        for (int r = 0; r < 2; ++r) {
            psum[r] += __shfl_xor_sync(0xffffffffu, psum[r], 1);
            psum[r] += __shfl_xor_sync(0xffffffffu, psum[r], 2);
            lrow[r] = lrow[r] * corr[r] + psum[r];
            mrow[r] = mnew[r];
        }
        #pragma unroll
        for (int j = 0; j < 8; ++j)
            #pragma unroll
            for (int x = 0; x < 4; ++x)
                Oacc[j][x] *= corr[x >> 1];

        // ---- O += P @ V ----
        #pragma unroll
        for (int kk2 = 0; kk2 < 4; ++kk2) {
            uint32_t pa[4];
            {
                __nv_bfloat162 t0 = __floats2bfloat162_rn(Sacc[2 * kk2][0], Sacc[2 * kk2][1]);
                __nv_bfloat162 t1 = __floats2bfloat162_rn(Sacc[2 * kk2][2], Sacc[2 * kk2][3]);
                __nv_bfloat162 t2 = __floats2bfloat162_rn(Sacc[2 * kk2 + 1][0], Sacc[2 * kk2 + 1][1]);
                __nv_bfloat162 t3 = __floats2bfloat162_rn(Sacc[2 * kk2 + 1][2], Sacc[2 * kk2 + 1][3]);
                pa[0] = *(uint32_t*)&t0; pa[1] = *(uint32_t*)&t1;
                pa[2] = *(uint32_t*)&t2; pa[3] = *(uint32_t*)&t3;
            }
            uint32_t bv[4][4];
            #pragma unroll
            for (int n16 = 0; n16 < 4; ++n16)
                ldsm_x4_t(bv[n16], vs_ + SW128((kk2 * 16 + rV) * 128 + n16 * 32 + nbV));
            #pragma unroll
            for (int j = 0; j < 8; ++j)
                mma_bf16(Oacc[j], pa, &bv[j >> 1][2 * (j & 1)]);
        }

        __syncthreads();
        if (t + 2 < NKV) {
            KV_ISSUE(t + 2, t & 1); CP_COMMIT();
            CP_WAIT_1();
            __syncthreads();
        } else if (t + 1 < NKV) {
            CP_WAIT_0();
            __syncthreads();
        }
    }
#undef KV_ISSUE

    // ---- epilogue: normalize, + residual, store fp32 ----
    const int gg = lane >> 2, cc = lane & 3;
    float inv[2] = {1.0f / lrow[0], 1.0f / lrow[1]};
    const int row0 = s0 + wid * 16 + gg;
    #pragma unroll
    for (int j = 0; j < 8; ++j) {
        int col = 8 * j + 2 * cc;
        size_t i0 = headoff + (size_t)row0 * DD + col;
        size_t i1 = headoff + (size_t)(row0 + 8) * DD + col;
        float2 r0 = *(const float2*)(Xres + i0);
        float2 r1 = *(const float2*)(Xres + i1);
        float2 o0 = {Oacc[j][0] * inv[0] + r0.x, Oacc[j][1] * inv[0] + r0.y};
        float2 o1 = {Oacc[j][2] * inv[1] + r1.x, Oacc[j][3] * inv[1] + r1.y};
        *(float2*)(Out + i0) = o0;
        *(float2*)(Out + i1) = o1;
    }
}

// ---------------------------------------------------------------------------
// Launch
// ---------------------------------------------------------------------------
extern "C" void kernel_launch(void* const* d_in, const int* in_sizes, int n_in,
                              void* d_out, int out_size)
{
    const float* queries = (const float*)d_in[0];
    const float* keys    = (const float*)d_in[1];
    const float* values  = (const float*)d_in[2];
    const float* Wq      = (const float*)d_in[3];
    const float* bq      = (const float*)d_in[4];
    const float* Wk      = (const float*)d_in[5];
    const float* bk      = (const float*)d_in[6];
    const float* Wv      = (const float*)d_in[7];
    const float* bv      = (const float*)d_in[8];
    float* out           = (float*)d_out;

    __nv_bfloat16 *dQp, *dKp, *dVp, *dQb, *dKb, *dVb, *dWqt, *dWkt, *dWvt;
    cudaGetSymbolAddress((void**)&dQp, g_Qp);
    cudaGetSymbolAddress((void**)&dKp, g_Kp);
    cudaGetSymbolAddress((void**)&dVp, g_Vp);
    cudaGetSymbolAddress((void**)&dQb, g_Qb);
    cudaGetSymbolAddress((void**)&dKb, g_Kb);
    cudaGetSymbolAddress((void**)&dVb, g_Vb);
    cudaGetSymbolAddress((void**)&dWqt, g_Wqt);
    cudaGetSymbolAddress((void**)&dWkt, g_Wkt);
    cudaGetSymbolAddress((void**)&dWvt, g_Wvt);

    // bf16 conversions
    f32_to_bf16_kernel<<<MM * DD / 1024, 256>>>(queries, dQb);
    f32_to_bf16_kernel<<<MM * DD / 1024, 256>>>(keys,    dKb);
    f32_to_bf16_kernel<<<MM * DD / 1024, 256>>>(values,  dVb);
    dim3 tgrid(DD / 32, DD / 32);
    dim3 tblk(32, 8);
    transpose_to_bf16_kernel<<<tgrid, tblk>>>(Wq, dWqt);
    transpose_to_bf16_kernel<<<tgrid, tblk>>>(Wk, dWkt);
    transpose_to_bf16_kernel<<<tgrid, tblk>>>(Wv, dWvt);

    // projections (HMMA, bf16 out)
    cudaFuncSetAttribute(gemm_bias_mma,
                         cudaFuncAttributeMaxDynamicSharedMemorySize, GEMM_SMEM);
    dim3 ggrid(DD / PBN, MM / PBM);   // (8, 32)
    gemm_bias_mma<<<ggrid, 256, GEMM_SMEM>>>(dQb, dWqt, bq, dQp);
    gemm_bias_mma<<<ggrid, 256, GEMM_SMEM>>>(dKb, dWkt, bk, dKp);
    gemm_bias_mma<<<ggrid, 256, GEMM_SMEM>>>(dVb, dWvt, bv, dVp);

    // attention (HMMA flash)
    cudaFuncSetAttribute(attn_mma,
                         cudaFuncAttributeMaxDynamicSharedMemorySize, ATTN_SMEM);
    dim3 agrid(SS / AQM, HH * BB);    // (16, 32)
    attn_mma<<<agrid, 256, ATTN_SMEM>>>(dQp, dKp, dVp, queries, out);
}